// round 1
// baseline (speedup 1.0000x reference)
#include <cuda_runtime.h>
#include <math.h>

#define T_TOK 4096
#define H_DIM 2048
#define I_DIM 1408
#define E_NUM 8
#define K_TOP 2
#define NPAIR (T_TOK * K_TOP)   // 8192

// ---------------- scratch (device globals: allocation-free) ----------------
__device__ int   g_off[E_NUM + 1];
__device__ int   g_rows_token[NPAIR];
__device__ float g_rows_w[NPAIR];
__device__ float g_inter[(size_t)NPAIR * I_DIM];   // ~46 MB fp32 scratch

// ---------------- routing: one block builds per-expert row lists -----------
__global__ void route_kernel(const int* __restrict__ idx,
                             const float* __restrict__ w) {
    __shared__ int cnt[E_NUM];
    __shared__ int off[E_NUM + 1];
    int tid = threadIdx.x;
    if (tid < E_NUM) cnt[tid] = 0;
    __syncthreads();
    for (int p = tid; p < NPAIR; p += blockDim.x)
        atomicAdd(&cnt[idx[p]], 1);
    __syncthreads();
    if (tid == 0) {
        int s = 0;
        for (int e = 0; e < E_NUM; e++) { off[e] = s; s += cnt[e]; }
        off[E_NUM] = s;
        for (int e = 0; e <= E_NUM; e++) g_off[e] = off[e];
    }
    __syncthreads();
    if (tid < E_NUM) cnt[tid] = off[tid];   // reuse as fill cursors
    __syncthreads();
    for (int p = tid; p < NPAIR; p += blockDim.x) {
        int e = idx[p];
        int pos = atomicAdd(&cnt[e], 1);
        g_rows_token[pos] = p >> 1;          // token = p / K_TOP
        g_rows_w[pos] = w[p];
    }
}

// ---------------- zero the output (scatter-add target) ---------------------
__global__ void zero_out_kernel(float4* __restrict__ out) {
    int i = blockIdx.x * blockDim.x + threadIdx.x;
    out[i] = make_float4(0.f, 0.f, 0.f, 0.f);
}

// ---------------- GEMM1: gate+up, fused SwiGLU -> g_inter ------------------
// Tile: 64 rows x 64 i-cols, k-step 16, 256 threads, 4x4 per thread (x2 accum)
__global__ __launch_bounds__(256)
void gemm1_kernel(const float* __restrict__ x,
                  const float* __restrict__ gate_w,
                  const float* __restrict__ up_w) {
    const int e    = blockIdx.z;
    const int base = g_off[e];
    const int Ne   = g_off[e + 1] - base;
    const int m0   = blockIdx.y * 64;
    if (m0 >= Ne) return;
    const int i0   = blockIdx.x * 64;

    __shared__ float As[16][64];
    __shared__ float Bg[16][64];
    __shared__ float Bu[16][64];

    const int tid = threadIdx.x;
    const int lr  = tid >> 2;           // 0..63  row-within-tile for loading
    const int lc  = (tid & 3) << 2;     // 0,4,8,12 k-offset (float4)
    const int tr  = (tid >> 4) << 2;    // compute rows  tr..tr+3
    const int tc  = (tid & 15) << 2;    // compute cols  tc..tc+3

    const bool rowvalid = (m0 + lr) < Ne;
    const float* a_ptr = rowvalid
        ? x + (size_t)g_rows_token[base + m0 + lr] * H_DIM : x;
    const float* bg_ptr = gate_w + ((size_t)e * I_DIM + i0 + lr) * H_DIM;
    const float* bu_ptr = up_w   + ((size_t)e * I_DIM + i0 + lr) * H_DIM;

    float accg[4][4] = {};
    float accu[4][4] = {};

    float4 av = rowvalid ? *(const float4*)(a_ptr + lc) : make_float4(0,0,0,0);
    float4 gv = *(const float4*)(bg_ptr + lc);
    float4 uv = *(const float4*)(bu_ptr + lc);

    for (int kt = 0; kt < H_DIM; kt += 16) {
        __syncthreads();
        As[lc+0][lr] = av.x; As[lc+1][lr] = av.y; As[lc+2][lr] = av.z; As[lc+3][lr] = av.w;
        Bg[lc+0][lr] = gv.x; Bg[lc+1][lr] = gv.y; Bg[lc+2][lr] = gv.z; Bg[lc+3][lr] = gv.w;
        Bu[lc+0][lr] = uv.x; Bu[lc+1][lr] = uv.y; Bu[lc+2][lr] = uv.z; Bu[lc+3][lr] = uv.w;
        __syncthreads();

        if (kt + 16 < H_DIM) {   // software prefetch next k-tile
            int k = kt + 16 + lc;
            av = rowvalid ? *(const float4*)(a_ptr + k) : make_float4(0,0,0,0);
            gv = *(const float4*)(bg_ptr + k);
            uv = *(const float4*)(bu_ptr + k);
        }

        #pragma unroll
        for (int kk = 0; kk < 16; kk++) {
            float4 a4 = *(const float4*)&As[kk][tr];
            float4 g4 = *(const float4*)&Bg[kk][tc];
            float4 u4 = *(const float4*)&Bu[kk][tc];
            float am[4] = {a4.x, a4.y, a4.z, a4.w};
            float gn[4] = {g4.x, g4.y, g4.z, g4.w};
            float un[4] = {u4.x, u4.y, u4.z, u4.w};
            #pragma unroll
            for (int mi = 0; mi < 4; mi++)
                #pragma unroll
                for (int ni = 0; ni < 4; ni++) {
                    accg[mi][ni] = fmaf(am[mi], gn[ni], accg[mi][ni]);
                    accu[mi][ni] = fmaf(am[mi], un[ni], accu[mi][ni]);
                }
        }
    }

    // epilogue: inter = silu(gate) * up
    #pragma unroll
    for (int mi = 0; mi < 4; mi++) {
        int rr = m0 + tr + mi;
        if (rr < Ne) {
            float* dst = g_inter + (size_t)(base + rr) * I_DIM + i0 + tc;
            #pragma unroll
            for (int ni = 0; ni < 4; ni++) {
                float g = accg[mi][ni];
                float s = g / (1.0f + expf(-g));
                dst[ni] = s * accu[mi][ni];
            }
        }
    }
}

// ---------------- GEMM2: inter @ down_w^T, weighted scatter-add ------------
__global__ __launch_bounds__(256)
void gemm2_kernel(const float* __restrict__ down_w,
                  float* __restrict__ out) {
    const int e    = blockIdx.z;
    const int base = g_off[e];
    const int Ne   = g_off[e + 1] - base;
    const int m0   = blockIdx.y * 64;
    if (m0 >= Ne) return;
    const int h0   = blockIdx.x * 64;

    __shared__ float As[16][64];
    __shared__ float Bd[16][64];

    const int tid = threadIdx.x;
    const int lr  = tid >> 2;
    const int lc  = (tid & 3) << 2;
    const int tr  = (tid >> 4) << 2;
    const int tc  = (tid & 15) << 2;

    const bool rowvalid = (m0 + lr) < Ne;
    const float* a_ptr = rowvalid
        ? g_inter + (size_t)(base + m0 + lr) * I_DIM : g_inter;
    const float* b_ptr = down_w + ((size_t)e * H_DIM + h0 + lr) * I_DIM;

    float acc[4][4] = {};

    float4 av = rowvalid ? *(const float4*)(a_ptr + lc) : make_float4(0,0,0,0);
    float4 bv = *(const float4*)(b_ptr + lc);

    for (int kt = 0; kt < I_DIM; kt += 16) {
        __syncthreads();
        As[lc+0][lr] = av.x; As[lc+1][lr] = av.y; As[lc+2][lr] = av.z; As[lc+3][lr] = av.w;
        Bd[lc+0][lr] = bv.x; Bd[lc+1][lr] = bv.y; Bd[lc+2][lr] = bv.z; Bd[lc+3][lr] = bv.w;
        __syncthreads();

        if (kt + 16 < I_DIM) {
            int k = kt + 16 + lc;
            av = rowvalid ? *(const float4*)(a_ptr + k) : make_float4(0,0,0,0);
            bv = *(const float4*)(b_ptr + k);
        }

        #pragma unroll
        for (int kk = 0; kk < 16; kk++) {
            float4 a4 = *(const float4*)&As[kk][tr];
            float4 b4 = *(const float4*)&Bd[kk][tc];
            float am[4] = {a4.x, a4.y, a4.z, a4.w};
            float bn[4] = {b4.x, b4.y, b4.z, b4.w};
            #pragma unroll
            for (int mi = 0; mi < 4; mi++)
                #pragma unroll
                for (int ni = 0; ni < 4; ni++)
                    acc[mi][ni] = fmaf(am[mi], bn[ni], acc[mi][ni]);
        }
    }

    #pragma unroll
    for (int mi = 0; mi < 4; mi++) {
        int rr = m0 + tr + mi;
        if (rr < Ne) {
            int   token = g_rows_token[base + rr];
            float wgt   = g_rows_w[base + rr];
            float* dst  = out + (size_t)token * H_DIM + h0 + tc;
            #pragma unroll
            for (int ni = 0; ni < 4; ni++)
                atomicAdd(&dst[ni], wgt * acc[mi][ni]);
        }
    }
}

// ---------------- launch ---------------------------------------------------
extern "C" void kernel_launch(void* const* d_in, const int* in_sizes, int n_in,
                              void* d_out, int out_size) {
    const float* hidden = (const float*)d_in[0];
    const int*   topk_i = (const int*)d_in[1];
    const float* topk_w = (const float*)d_in[2];
    const float* gate_w = (const float*)d_in[3];
    const float* up_w   = (const float*)d_in[4];
    const float* down_w = (const float*)d_in[5];
    float* out = (float*)d_out;

    route_kernel<<<1, 256>>>(topk_i, topk_w);

    int n4 = (T_TOK * H_DIM) / 4;                 // 2,097,152 float4
    zero_out_kernel<<<n4 / 256, 256>>>((float4*)out);

    dim3 g1(I_DIM / 64, NPAIR / 64, E_NUM);       // (22, 128, 8)
    gemm1_kernel<<<g1, 256>>>(hidden, gate_w, up_w);

    dim3 g2(H_DIM / 64, NPAIR / 64, E_NUM);       // (32, 128, 8)
    gemm2_kernel<<<g2, 256>>>(down_w, out);
}

// round 3
// speedup vs baseline: 3.7031x; 3.7031x over previous
#include <cuda_runtime.h>
#include <cstdint>
#include <math.h>

#define T_TOK 4096
#define H_DIM 2048
#define I_DIM 1408
#define E_NUM 8
#define NPAIR 8192

// ---------------- scratch (device globals) ----------------
__device__ int   g_off[E_NUM + 1];
__device__ int   g_rows_token[NPAIR];
__device__ int   g_pos[NPAIR];
__device__ float g_Ax[(size_t)NPAIR * H_DIM];          // gathered + rna activations
__device__ float g_inter[(size_t)NPAIR * I_DIM];       // swiglu out (rna)
__device__ float g_out2[(size_t)NPAIR * H_DIM];        // per-pair down output
__device__ float g_gate_r[(size_t)E_NUM * I_DIM * H_DIM];  // rna weights
__device__ float g_up_r[(size_t)E_NUM * I_DIM * H_DIM];
__device__ float g_down_r[(size_t)E_NUM * H_DIM * I_DIM];

// ---------------- helpers ----------------
__device__ __forceinline__ uint32_t smem_u32(const void* p) {
    uint32_t a;
    asm("{ .reg .u64 t; cvta.to.shared.u64 t, %1; cvt.u32.u64 %0, t; }" : "=r"(a) : "l"(p));
    return a;
}
__device__ __forceinline__ float rna(float x) {
    uint32_t r;
    asm("cvt.rna.tf32.f32 %0, %1;" : "=r"(r) : "f"(x));
    return __uint_as_float(r);
}
__device__ __forceinline__ void cpa16(uint32_t dst, const float* src) {
    asm volatile("cp.async.cg.shared.global [%0], [%1], 16;" :: "r"(dst), "l"(src));
}
#define CPA_COMMIT() asm volatile("cp.async.commit_group;" ::: "memory")
#define CPA_WAIT1()  asm volatile("cp.async.wait_group 1;" ::: "memory")
#define CPA_WAIT0()  asm volatile("cp.async.wait_group 0;" ::: "memory")

__device__ __forceinline__ void mma_tf32(float c[4], const uint32_t a[4], const uint32_t b[2]) {
    asm volatile("mma.sync.aligned.m16n8k8.row.col.f32.tf32.tf32.f32 "
                 "{%0,%1,%2,%3}, {%4,%5,%6,%7}, {%8,%9}, {%0,%1,%2,%3};"
                 : "+f"(c[0]), "+f"(c[1]), "+f"(c[2]), "+f"(c[3])
                 : "r"(a[0]), "r"(a[1]), "r"(a[2]), "r"(a[3]), "r"(b[0]), "r"(b[1]));
}

// SMEM tile geometry: per stage A[128][36] + B[128][36] floats (pad 4 kills conflicts)
#define LDP 36
#define STAGE_F 9216             // floats per stage (2 * 128 * 36)
#define STAGE_B 36864            // bytes per stage
#define B_OFF_F 4608             // B region float offset within a stage
#define NSTAGE 3
#define SMEM_BYTES (NSTAGE * STAGE_B)   // 110592

#define SA(smf, s, r, c) (smf)[(s) * STAGE_F + (r) * LDP + (c)]
#define SB(smf, s, n, c) (smf)[(s) * STAGE_F + B_OFF_F + (n) * LDP + (c)]

// warp-tile compute: 64x32 via 4x4 m16n8k8 tiles, K=32 chunk
__device__ __forceinline__ void tile_compute(const float* smf, int s, int wm, int wn,
                                             int lane, float acc[4][4][4]) {
    const int lr = lane >> 2, lc = lane & 3;
    #pragma unroll
    for (int kk = 0; kk < 4; kk++) {
        const int k = kk * 8;
        uint32_t a[4][4], b[4][2];
        #pragma unroll
        for (int mt = 0; mt < 4; mt++) {
            int r0 = wm + mt * 16 + lr;
            a[mt][0] = __float_as_uint(SA(smf, s, r0,     k + lc));
            a[mt][1] = __float_as_uint(SA(smf, s, r0 + 8, k + lc));
            a[mt][2] = __float_as_uint(SA(smf, s, r0,     k + 4 + lc));
            a[mt][3] = __float_as_uint(SA(smf, s, r0 + 8, k + 4 + lc));
        }
        #pragma unroll
        for (int nt = 0; nt < 4; nt++) {
            int c0 = wn + nt * 8 + lr;
            b[nt][0] = __float_as_uint(SB(smf, s, c0, k + lc));
            b[nt][1] = __float_as_uint(SB(smf, s, c0, k + 4 + lc));
        }
        #pragma unroll
        for (int mt = 0; mt < 4; mt++)
            #pragma unroll
            for (int nt = 0; nt < 4; nt++)
                mma_tf32(acc[mt][nt], a[mt], b[nt]);
    }
}

// ---------------- routing ----------------
__global__ void route_kernel(const int* __restrict__ idx) {
    __shared__ int cnt[E_NUM];
    __shared__ int off[E_NUM + 1];
    int tid = threadIdx.x;
    if (tid < E_NUM) cnt[tid] = 0;
    __syncthreads();
    for (int p = tid; p < NPAIR; p += blockDim.x) atomicAdd(&cnt[idx[p]], 1);
    __syncthreads();
    if (tid == 0) {
        int s = 0;
        for (int e = 0; e < E_NUM; e++) { off[e] = s; s += cnt[e]; }
        off[E_NUM] = s;
        for (int e = 0; e <= E_NUM; e++) g_off[e] = off[e];
    }
    __syncthreads();
    if (tid < E_NUM) cnt[tid] = off[tid];
    __syncthreads();
    for (int p = tid; p < NPAIR; p += blockDim.x) {
        int e = idx[p];
        int pos = atomicAdd(&cnt[e], 1);
        g_rows_token[pos] = p >> 1;
        g_pos[p] = pos;
    }
}

// ---------------- gather + rna ----------------
__global__ void gather_kernel(const float* __restrict__ x) {
    int pos = blockIdx.x;
    int tkn = g_rows_token[pos];
    const float4* src = (const float4*)(x + (size_t)tkn * H_DIM);
    float4* dst = (float4*)(g_Ax + (size_t)pos * H_DIM);
    for (int j = threadIdx.x; j < H_DIM / 4; j += 256) {
        float4 v = src[j];
        v.x = rna(v.x); v.y = rna(v.y); v.z = rna(v.z); v.w = rna(v.w);
        dst[j] = v;
    }
}

// ---------------- weight rna pre-pass ----------------
__global__ void round_kernel(const float4* __restrict__ src, float4* __restrict__ dst, int n4) {
    int i = blockIdx.x * blockDim.x + threadIdx.x;
    if (i < n4) {
        float4 v = src[i];
        v.x = rna(v.x); v.y = rna(v.y); v.z = rna(v.z); v.w = rna(v.w);
        dst[i] = v;
    }
}

// ---------------- GEMM1: rows x 64 i-cols, gate/up interleaved, SwiGLU ------
#define NC1 (H_DIM / 32)   // 64

__global__ void __launch_bounds__(256, 2)
gemm1_kernel() {
    const int e = blockIdx.z;
    const int base = g_off[e], Ne = g_off[e + 1] - base;
    const int m0 = blockIdx.y * 128;
    if (m0 >= Ne) return;
    const int i0 = blockIdx.x * 64;

    extern __shared__ float smf[];
    const uint32_t sb = smem_u32(smf);
    const int tid = threadIdx.x, lane = tid & 31, wid = tid >> 5;
    const int wm = (wid & 1) * 64, wn = (wid >> 1) * 32;

    // load mapping: 256 threads x 8 cp.async(16B) per stage
    const int lrow = tid >> 3, seg = tid & 7;
    const float* aptr[4];
    const float* bptr[4];
    #pragma unroll
    for (int r4 = 0; r4 < 4; r4++) {
        int rr = lrow + 32 * r4;
        int am = m0 + rr; if (am > Ne - 1) am = Ne - 1;
        aptr[r4] = g_Ax + (size_t)(base + am) * H_DIM + seg * 4;
        int ii = i0 + (rr >> 1);
        const float* wbase = (rr & 1) ? g_up_r : g_gate_r;
        bptr[r4] = wbase + ((size_t)e * I_DIM + ii) * H_DIM + seg * 4;
    }

    float acc[4][4][4];
    #pragma unroll
    for (int mt = 0; mt < 4; mt++)
        #pragma unroll
        for (int nt = 0; nt < 4; nt++)
            #pragma unroll
            for (int q = 0; q < 4; q++) acc[mt][nt][q] = 0.f;

    // prologue: stages 0, 1
    #pragma unroll
    for (int s = 0; s < 2; s++) {
        uint32_t st = sb + s * STAGE_B;
        int kt = s * 32;
        #pragma unroll
        for (int r4 = 0; r4 < 4; r4++) {
            int rr = lrow + 32 * r4;
            cpa16(st + rr * 144 + seg * 16, aptr[r4] + kt);
            cpa16(st + 18432 + rr * 144 + seg * 16, bptr[r4] + kt);
        }
        CPA_COMMIT();
    }

    for (int i = 0; i < NC1; i++) {
        if (i >= NC1 - 1) CPA_WAIT0(); else CPA_WAIT1();
        __syncthreads();
        if (i + 2 < NC1) {
            int s = (i + 2) % NSTAGE;
            uint32_t st = sb + s * STAGE_B;
            int kt = (i + 2) * 32;
            #pragma unroll
            for (int r4 = 0; r4 < 4; r4++) {
                int rr = lrow + 32 * r4;
                cpa16(st + rr * 144 + seg * 16, aptr[r4] + kt);
                cpa16(st + 18432 + rr * 144 + seg * 16, bptr[r4] + kt);
            }
            CPA_COMMIT();
        }
        tile_compute(smf, i % NSTAGE, wm, wn, lane, acc);
        __syncthreads();
    }

    // epilogue: silu(gate)*up from register pairs (c0,c1)/(c2,c3)
    const int lr = lane >> 2, lc = lane & 3;
    #pragma unroll
    for (int mt = 0; mt < 4; mt++) {
        int r = m0 + wm + mt * 16 + lr;
        #pragma unroll
        for (int nt = 0; nt < 4; nt++) {
            int ii = i0 + (wn >> 1) + nt * 4 + lc;
            if (r < Ne) {
                float g = acc[mt][nt][0], u = acc[mt][nt][1];
                g_inter[(size_t)(base + r) * I_DIM + ii] = rna(g / (1.f + __expf(-g)) * u);
            }
            if (r + 8 < Ne) {
                float g = acc[mt][nt][2], u = acc[mt][nt][3];
                g_inter[(size_t)(base + r + 8) * I_DIM + ii] = rna(g / (1.f + __expf(-g)) * u);
            }
        }
    }
}

// ---------------- GEMM2: inter @ down^T ----------------
#define NC2 (I_DIM / 32)   // 44

__global__ void __launch_bounds__(256, 2)
gemm2_kernel() {
    const int e = blockIdx.z;
    const int base = g_off[e], Ne = g_off[e + 1] - base;
    const int m0 = blockIdx.y * 128;
    if (m0 >= Ne) return;
    const int h0 = blockIdx.x * 128;

    extern __shared__ float smf[];
    const uint32_t sb = smem_u32(smf);
    const int tid = threadIdx.x, lane = tid & 31, wid = tid >> 5;
    const int wm = (wid & 1) * 64, wn = (wid >> 1) * 32;

    const int lrow = tid >> 3, seg = tid & 7;
    const float* aptr[4];
    const float* bptr[4];
    #pragma unroll
    for (int r4 = 0; r4 < 4; r4++) {
        int rr = lrow + 32 * r4;
        int am = m0 + rr; if (am > Ne - 1) am = Ne - 1;
        aptr[r4] = g_inter + (size_t)(base + am) * I_DIM + seg * 4;
        bptr[r4] = g_down_r + ((size_t)e * H_DIM + h0 + rr) * I_DIM + seg * 4;
    }

    float acc[4][4][4];
    #pragma unroll
    for (int mt = 0; mt < 4; mt++)
        #pragma unroll
        for (int nt = 0; nt < 4; nt++)
            #pragma unroll
            for (int q = 0; q < 4; q++) acc[mt][nt][q] = 0.f;

    #pragma unroll
    for (int s = 0; s < 2; s++) {
        uint32_t st = sb + s * STAGE_B;
        int kt = s * 32;
        #pragma unroll
        for (int r4 = 0; r4 < 4; r4++) {
            int rr = lrow + 32 * r4;
            cpa16(st + rr * 144 + seg * 16, aptr[r4] + kt);
            cpa16(st + 18432 + rr * 144 + seg * 16, bptr[r4] + kt);
        }
        CPA_COMMIT();
    }

    for (int i = 0; i < NC2; i++) {
        if (i >= NC2 - 1) CPA_WAIT0(); else CPA_WAIT1();
        __syncthreads();
        if (i + 2 < NC2) {
            int s = (i + 2) % NSTAGE;
            uint32_t st = sb + s * STAGE_B;
            int kt = (i + 2) * 32;
            #pragma unroll
            for (int r4 = 0; r4 < 4; r4++) {
                int rr = lrow + 32 * r4;
                cpa16(st + rr * 144 + seg * 16, aptr[r4] + kt);
                cpa16(st + 18432 + rr * 144 + seg * 16, bptr[r4] + kt);
            }
            CPA_COMMIT();
        }
        tile_compute(smf, i % NSTAGE, wm, wn, lane, acc);
        __syncthreads();
    }

    const int lr = lane >> 2, lc = lane & 3;
    #pragma unroll
    for (int mt = 0; mt < 4; mt++) {
        int r = m0 + wm + mt * 16 + lr;
        #pragma unroll
        for (int nt = 0; nt < 4; nt++) {
            int h = h0 + wn + nt * 8 + 2 * lc;
            if (r < Ne)
                *(float2*)(g_out2 + (size_t)(base + r) * H_DIM + h) =
                    make_float2(acc[mt][nt][0], acc[mt][nt][1]);
            if (r + 8 < Ne)
                *(float2*)(g_out2 + (size_t)(base + r + 8) * H_DIM + h) =
                    make_float2(acc[mt][nt][2], acc[mt][nt][3]);
        }
    }
}

// ---------------- combine ----------------
__global__ void combine_kernel(const float* __restrict__ w, float* __restrict__ out) {
    int t = blockIdx.x;
    float w0 = w[2 * t], w1 = w[2 * t + 1];
    const float4* a = (const float4*)(g_out2 + (size_t)g_pos[2 * t] * H_DIM);
    const float4* b = (const float4*)(g_out2 + (size_t)g_pos[2 * t + 1] * H_DIM);
    float4* o = (float4*)(out + (size_t)t * H_DIM);
    for (int j = threadIdx.x; j < H_DIM / 4; j += 256) {
        float4 va = a[j], vb = b[j], r;
        r.x = w0 * va.x + w1 * vb.x;
        r.y = w0 * va.y + w1 * vb.y;
        r.z = w0 * va.z + w1 * vb.z;
        r.w = w0 * va.w + w1 * vb.w;
        o[j] = r;
    }
}

// ---------------- launch ----------------
extern "C" void kernel_launch(void* const* d_in, const int* in_sizes, int n_in,
                              void* d_out, int out_size) {
    const float* hidden = (const float*)d_in[0];
    const int*   topk_i = (const int*)d_in[1];
    const float* topk_w = (const float*)d_in[2];
    const float* gate_w = (const float*)d_in[3];
    const float* up_w   = (const float*)d_in[4];
    const float* down_w = (const float*)d_in[5];
    float* out = (float*)d_out;

    cudaFuncSetAttribute(gemm1_kernel, cudaFuncAttributeMaxDynamicSharedMemorySize, SMEM_BYTES);
    cudaFuncSetAttribute(gemm2_kernel, cudaFuncAttributeMaxDynamicSharedMemorySize, SMEM_BYTES);

    route_kernel<<<1, 256>>>(topk_i);
    gather_kernel<<<NPAIR, 256>>>(hidden);

    int wn4 = (E_NUM * I_DIM * H_DIM) / 4;   // 5,767,168
    float* gr; cudaGetSymbolAddress((void**)&gr, g_gate_r);
    float* ur; cudaGetSymbolAddress((void**)&ur, g_up_r);
    float* dr; cudaGetSymbolAddress((void**)&dr, g_down_r);
    round_kernel<<<(wn4 + 255) / 256, 256>>>((const float4*)gate_w, (float4*)gr, wn4);
    round_kernel<<<(wn4 + 255) / 256, 256>>>((const float4*)up_w,   (float4*)ur, wn4);
    round_kernel<<<(wn4 + 255) / 256, 256>>>((const float4*)down_w, (float4*)dr, wn4);

    dim3 g1(I_DIM / 64, NPAIR / 128, E_NUM);   // (22, 64, 8)
    gemm1_kernel<<<g1, 256, SMEM_BYTES>>>();

    dim3 g2(H_DIM / 128, NPAIR / 128, E_NUM);  // (16, 64, 8)
    gemm2_kernel<<<g2, 256, SMEM_BYTES>>>();

    combine_kernel<<<T_TOK, 256>>>(topk_w, out);
}

// round 4
// speedup vs baseline: 4.5614x; 1.2318x over previous
#include <cuda_runtime.h>
#include <cstdint>
#include <math.h>

#define T_TOK 4096
#define H_DIM 2048
#define I_DIM 1408
#define E_NUM 8
#define NPAIR 8192
#define NROWS 9216            // NPAIR + E_NUM*128 padding

// ---------------- scratch (device globals) ----------------
__device__ int   g_off[E_NUM + 1];        // padded per-expert offsets (mult of 128)
__device__ int   g_rows_token[NROWS];
__device__ int   g_pos[NPAIR];            // pair -> padded slot
__device__ float g_Ax[(size_t)NROWS * H_DIM];                // AFRAG activations
__device__ float g_inter[(size_t)NROWS * I_DIM];             // AFRAG swiglu out
__device__ float g_out2[(size_t)NROWS * H_DIM];              // row-major down out
__device__ float g_w1[(size_t)E_NUM * 2 * I_DIM * H_DIM];    // BFRAG gate/up interleaved
__device__ float g_dw[(size_t)E_NUM * H_DIM * I_DIM];        // BFRAG down

// ---------------- helpers ----------------
__device__ __forceinline__ uint32_t smem_u32(const void* p) {
    uint32_t a;
    asm("{ .reg .u64 t; cvta.to.shared.u64 t, %1; cvt.u32.u64 %0, t; }" : "=r"(a) : "l"(p));
    return a;
}
__device__ __forceinline__ float rna(float x) {
    uint32_t r;
    asm("cvt.rna.tf32.f32 %0, %1;" : "=r"(r) : "f"(x));
    return __uint_as_float(r);
}
__device__ __forceinline__ void cpa16(uint32_t dst, const float* src) {
    asm volatile("cp.async.cg.shared.global [%0], [%1], 16;" :: "r"(dst), "l"(src));
}
#define CPA_COMMIT() asm volatile("cp.async.commit_group;" ::: "memory")
#define CPA_WAIT1()  asm volatile("cp.async.wait_group 1;" ::: "memory")
#define CPA_WAIT0()  asm volatile("cp.async.wait_group 0;" ::: "memory")
#define FU(x) __float_as_uint(x)

__device__ __forceinline__ void mma_tf32(float c[4], const uint32_t a[4], uint32_t b0, uint32_t b1) {
    asm volatile("mma.sync.aligned.m16n8k8.row.col.f32.tf32.tf32.f32 "
                 "{%0,%1,%2,%3}, {%4,%5,%6,%7}, {%8,%9}, {%0,%1,%2,%3};"
                 : "+f"(c[0]), "+f"(c[1]), "+f"(c[2]), "+f"(c[3])
                 : "r"(a[0]), "r"(a[1]), "r"(a[2]), "r"(a[3]), "r"(b0), "r"(b1));
}

#define STAGE_B 32768
#define NSTAGE 3
#define SMEM_BYTES (NSTAGE * STAGE_B)   // 98304

// ---------------- routing (padded offsets) ----------------
__global__ void route_kernel(const int* __restrict__ idx) {
    __shared__ int cnt[E_NUM];
    __shared__ int off[E_NUM + 1];
    int tid = threadIdx.x;
    for (int p = tid; p < NROWS; p += 256) g_rows_token[p] = 0;  // pad slots -> token 0
    if (tid < E_NUM) cnt[tid] = 0;
    __syncthreads();
    for (int p = tid; p < NPAIR; p += 256) atomicAdd(&cnt[idx[p]], 1);
    __syncthreads();
    if (tid == 0) {
        int s = 0;
        for (int e = 0; e < E_NUM; e++) { off[e] = s; s += ((cnt[e] + 127) >> 7) << 7; }
        off[E_NUM] = s;
        for (int e = 0; e <= E_NUM; e++) g_off[e] = off[e];
    }
    __syncthreads();
    if (tid < E_NUM) cnt[tid] = off[tid];
    __syncthreads();
    for (int p = tid; p < NPAIR; p += 256) {
        int e = idx[p];
        int pos = atomicAdd(&cnt[e], 1);
        g_rows_token[pos] = p >> 1;
        g_pos[p] = pos;
    }
}

// ---------------- gather -> AFRAG (+rna) ----------------
// AFRAG: float4 idx = (mb*(K/8) + k8)*32 + lane ; lane=(r%8)*4 + (kc%4)
// float4 = [ (lr,lc), (lr+8,lc), (lr,4+lc), (lr+8,4+lc) ]
__global__ void gather_kernel(const float* __restrict__ x) {
    int mb = blockIdx.x;                       // 0..575
    int tid = threadIdx.x, lane = tid & 31, ws = tid >> 5;
    int lr = lane >> 2, lc = lane & 3;
    const float* r0 = x + (size_t)g_rows_token[mb * 16 + lr] * H_DIM;
    const float* r1 = x + (size_t)g_rows_token[mb * 16 + 8 + lr] * H_DIM;
    float4* dst = (float4*)g_Ax + (size_t)mb * 256 * 32 + lane;
    #pragma unroll 4
    for (int it = 0; it < 32; it++) {
        int k8 = ws + 8 * it;
        int k = k8 * 8;
        float4 v;
        v.x = rna(r0[k + lc]);
        v.y = rna(r1[k + lc]);
        v.z = rna(r0[k + 4 + lc]);
        v.w = rna(r1[k + 4 + lc]);
        dst[(size_t)k8 * 32] = v;
    }
}

// ---------------- weights -> BFRAG (+rna) ----------------
// BFRAG: float4 idx = (nb*(K/16) + k16)*32 + lane ; lane=(n%8)*4 + (k%4)
// float4 = [ B[n][16k16+lc], [..+4+lc], [..+8+lc], [..+12+lc] ]
__global__ void permw1_kernel(const float* __restrict__ gate_w, const float* __restrict__ up_w) {
    int bid = blockIdx.x;                      // e*352 + nb
    int e = bid / 352, nb = bid % 352;
    int tid = threadIdx.x, lane = tid & 31, ws = tid >> 5;
    int lr = lane >> 2, lc = lane & 3;
    int n = nb * 8 + lr, i = n >> 1;
    const float* src = ((n & 1) ? up_w : gate_w) + ((size_t)e * I_DIM + i) * H_DIM;
    float4* dst = (float4*)g_w1 + (size_t)bid * 128 * 32 + lane;
    #pragma unroll 4
    for (int it = 0; it < 16; it++) {
        int k16 = ws + 8 * it;
        int k = k16 * 16;
        float4 v;
        v.x = rna(src[k + lc]);
        v.y = rna(src[k + 4 + lc]);
        v.z = rna(src[k + 8 + lc]);
        v.w = rna(src[k + 12 + lc]);
        dst[(size_t)k16 * 32] = v;
    }
}

__global__ void permdw_kernel(const float* __restrict__ down_w) {
    int bid = blockIdx.x;                      // e*256 + nb
    int e = bid >> 8, nb = bid & 255;
    int tid = threadIdx.x, lane = tid & 31, ws = tid >> 5;
    int lr = lane >> 2, lc = lane & 3;
    int h = nb * 8 + lr;
    const float* src = down_w + ((size_t)e * H_DIM + h) * I_DIM;
    float4* dst = (float4*)g_dw + (size_t)bid * 88 * 32 + lane;
    #pragma unroll
    for (int it = 0; it < 11; it++) {
        int k16 = ws + 8 * it;
        int k = k16 * 16;
        float4 v;
        v.x = rna(src[k + lc]);
        v.y = rna(src[k + 4 + lc]);
        v.z = rna(src[k + 8 + lc]);
        v.w = rna(src[k + 12 + lc]);
        dst[(size_t)k16 * 32] = v;
    }
}

// ---------------- GEMM core (shared by both) ----------------
// per-chunk compute: warp tile 64x32, 16 m16n8k8 per kk, 4 kk
__device__ __forceinline__ void tile_compute(const float* stg, int mtb, int ntb,
                                             int lane, float acc[4][4][4]) {
    const float* stgB = stg + 4096;
    float4 bfr[4];
    #pragma unroll
    for (int kk = 0; kk < 4; kk++) {
        if ((kk & 1) == 0) {
            #pragma unroll
            for (int nt = 0; nt < 4; nt++)
                bfr[nt] = *(const float4*)(stgB + ((ntb + nt) * 2 + (kk >> 1)) * 128 + lane * 4);
        }
        #pragma unroll
        for (int mt = 0; mt < 4; mt++) {
            float4 af = *(const float4*)(stg + ((mtb + mt) * 4 + kk) * 128 + lane * 4);
            uint32_t a[4] = {FU(af.x), FU(af.y), FU(af.z), FU(af.w)};
            #pragma unroll
            for (int nt = 0; nt < 4; nt++) {
                if ((kk & 1) == 0) mma_tf32(acc[mt][nt], a, FU(bfr[nt].x), FU(bfr[nt].y));
                else               mma_tf32(acc[mt][nt], a, FU(bfr[nt].z), FU(bfr[nt].w));
            }
        }
    }
}

// ---------------- GEMM1: Ax @ [gate;up]^T (interleaved), SwiGLU -> AFRAG ----
#define NC1 64

__global__ void __launch_bounds__(256, 2)
gemm1_kernel() {
    const int e = blockIdx.z;
    const int base = g_off[e];
    const int Npad = g_off[e + 1] - base;
    const int m0 = blockIdx.y * 128;
    if (m0 >= Npad) return;
    const int bx = blockIdx.x;                 // i-block: 64 i = 128 n = 16 nb
    const int mb0 = (base + m0) >> 4;          // global m16 block base (base mult of 128)
    const int nb0 = bx * 16;

    extern __shared__ char smem[];
    const uint32_t sb = smem_u32(smem);
    const int tid = threadIdx.x, lane = tid & 31, wid = tid >> 5;
    const int mtb = (wid & 1) * 4, ntb = (wid >> 1) * 4;

    // cp.async assignments: 4 A-frag blocks + 4 B-frag blocks per thread
    uint32_t a_off[4], b_off[4];
    const float* a_src[4];
    const float* b_src[4];
    #pragma unroll
    for (int j = 0; j < 4; j++) {
        int idx = tid + j * 256;
        int fb = idx >> 5, ln = idx & 31;
        int mbl = fb >> 2, k8l = fb & 3;
        a_off[j] = (mbl * 4 + k8l) * 512 + ln * 16;
        a_src[j] = g_Ax + (((size_t)(mb0 + mbl) * 256 + k8l) * 32 + ln) * 4;
        int nbl = fb >> 1, k16l = fb & 1;
        b_off[j] = 16384 + (nbl * 2 + k16l) * 512 + ln * 16;
        b_src[j] = g_w1 + (((size_t)(e * 352 + nb0 + nbl) * 128 + k16l) * 32 + ln) * 4;
    }

    float acc[4][4][4];
    #pragma unroll
    for (int mt = 0; mt < 4; mt++)
        #pragma unroll
        for (int nt = 0; nt < 4; nt++)
            #pragma unroll
            for (int q = 0; q < 4; q++) acc[mt][nt][q] = 0.f;

    // prologue: chunks 0,1
    #pragma unroll
    for (int s = 0; s < 2; s++) {
        uint32_t st = sb + s * STAGE_B;
        #pragma unroll
        for (int j = 0; j < 4; j++) {
            cpa16(st + a_off[j], a_src[j] + s * 512);
            cpa16(st + b_off[j], b_src[j] + s * 256);
        }
        CPA_COMMIT();
    }
    #pragma unroll
    for (int j = 0; j < 4; j++) { a_src[j] += 1024; b_src[j] += 512; }

    for (int c = 0; c < NC1; c++) {
        if (c >= NC1 - 1) CPA_WAIT0(); else CPA_WAIT1();
        __syncthreads();
        if (c + 2 < NC1) {
            uint32_t st = sb + ((c + 2) % NSTAGE) * STAGE_B;
            #pragma unroll
            for (int j = 0; j < 4; j++) {
                cpa16(st + a_off[j], a_src[j]);
                cpa16(st + b_off[j], b_src[j]);
                a_src[j] += 512; b_src[j] += 256;
            }
            CPA_COMMIT();
        }
        tile_compute((const float*)(smem + (c % NSTAGE) * STAGE_B), mtb, ntb, lane, acc);
    }

    // epilogue: silu(gate)*up -> g_inter AFRAG (coalesced STG.128)
    const int i_k8base = bx * 8 + (wid >> 1) * 2;
    const int mbGbase = mb0 + (wid & 1) * 4;
    #pragma unroll
    for (int mt = 0; mt < 4; mt++) {
        #pragma unroll
        for (int b = 0; b < 2; b++) {
            float g, u;
            float4 v;
            g = acc[mt][2 * b][0];     u = acc[mt][2 * b][1];
            v.x = rna(g / (1.f + __expf(-g)) * u);
            g = acc[mt][2 * b][2];     u = acc[mt][2 * b][3];
            v.y = rna(g / (1.f + __expf(-g)) * u);
            g = acc[mt][2 * b + 1][0]; u = acc[mt][2 * b + 1][1];
            v.z = rna(g / (1.f + __expf(-g)) * u);
            g = acc[mt][2 * b + 1][2]; u = acc[mt][2 * b + 1][3];
            v.w = rna(g / (1.f + __expf(-g)) * u);
            *((float4*)g_inter + ((size_t)(mbGbase + mt) * 176 + i_k8base + b) * 32 + lane) = v;
        }
    }
}

// ---------------- GEMM2: inter @ down^T -> row-major g_out2 ----------------
#define NC2 44

__global__ void __launch_bounds__(256, 2)
gemm2_kernel() {
    const int e = blockIdx.z;
    const int base = g_off[e];
    const int Npad = g_off[e + 1] - base;
    const int m0 = blockIdx.y * 128;
    if (m0 >= Npad) return;
    const int bx = blockIdx.x;                 // h-block of 128
    const int mb0 = (base + m0) >> 4;
    const int nb0 = bx * 16;
    const int h0 = bx * 128;

    extern __shared__ char smem[];
    const uint32_t sb = smem_u32(smem);
    const int tid = threadIdx.x, lane = tid & 31, wid = tid >> 5;
    const int mtb = (wid & 1) * 4, ntb = (wid >> 1) * 4;

    uint32_t a_off[4], b_off[4];
    const float* a_src[4];
    const float* b_src[4];
    #pragma unroll
    for (int j = 0; j < 4; j++) {
        int idx = tid + j * 256;
        int fb = idx >> 5, ln = idx & 31;
        int mbl = fb >> 2, k8l = fb & 3;
        a_off[j] = (mbl * 4 + k8l) * 512 + ln * 16;
        a_src[j] = g_inter + (((size_t)(mb0 + mbl) * 176 + k8l) * 32 + ln) * 4;
        int nbl = fb >> 1, k16l = fb & 1;
        b_off[j] = 16384 + (nbl * 2 + k16l) * 512 + ln * 16;
        b_src[j] = g_dw + (((size_t)(e * 256 + nb0 + nbl) * 88 + k16l) * 32 + ln) * 4;
    }

    float acc[4][4][4];
    #pragma unroll
    for (int mt = 0; mt < 4; mt++)
        #pragma unroll
        for (int nt = 0; nt < 4; nt++)
            #pragma unroll
            for (int q = 0; q < 4; q++) acc[mt][nt][q] = 0.f;

    #pragma unroll
    for (int s = 0; s < 2; s++) {
        uint32_t st = sb + s * STAGE_B;
        #pragma unroll
        for (int j = 0; j < 4; j++) {
            cpa16(st + a_off[j], a_src[j] + s * 512);
            cpa16(st + b_off[j], b_src[j] + s * 256);
        }
        CPA_COMMIT();
    }
    #pragma unroll
    for (int j = 0; j < 4; j++) { a_src[j] += 1024; b_src[j] += 512; }

    for (int c = 0; c < NC2; c++) {
        if (c >= NC2 - 1) CPA_WAIT0(); else CPA_WAIT1();
        __syncthreads();
        if (c + 2 < NC2) {
            uint32_t st = sb + ((c + 2) % NSTAGE) * STAGE_B;
            #pragma unroll
            for (int j = 0; j < 4; j++) {
                cpa16(st + a_off[j], a_src[j]);
                cpa16(st + b_off[j], b_src[j]);
                a_src[j] += 512; b_src[j] += 256;
            }
            CPA_COMMIT();
        }
        tile_compute((const float*)(smem + (c % NSTAGE) * STAGE_B), mtb, ntb, lane, acc);
    }

    // epilogue: row-major float2 stores (no bound checks; padded buffer)
    const int lr = lane >> 2, lc = lane & 3;
    const int rbase = base + m0 + (wid & 1) * 64 + lr;
    #pragma unroll
    for (int mt = 0; mt < 4; mt++) {
        int r = rbase + mt * 16;
        #pragma unroll
        for (int nt = 0; nt < 4; nt++) {
            int h = h0 + (wid >> 1) * 32 + nt * 8 + 2 * lc;
            *(float2*)(g_out2 + (size_t)r * H_DIM + h) =
                make_float2(acc[mt][nt][0], acc[mt][nt][1]);
            *(float2*)(g_out2 + (size_t)(r + 8) * H_DIM + h) =
                make_float2(acc[mt][nt][2], acc[mt][nt][3]);
        }
    }
}

// ---------------- combine ----------------
__global__ void combine_kernel(const float* __restrict__ w, float* __restrict__ out) {
    int t = blockIdx.x;
    float w0 = w[2 * t], w1 = w[2 * t + 1];
    const float4* a = (const float4*)(g_out2 + (size_t)g_pos[2 * t] * H_DIM);
    const float4* b = (const float4*)(g_out2 + (size_t)g_pos[2 * t + 1] * H_DIM);
    float4* o = (float4*)(out + (size_t)t * H_DIM);
    for (int j = threadIdx.x; j < H_DIM / 4; j += 256) {
        float4 va = a[j], vb = b[j], r;
        r.x = w0 * va.x + w1 * vb.x;
        r.y = w0 * va.y + w1 * vb.y;
        r.z = w0 * va.z + w1 * vb.z;
        r.w = w0 * va.w + w1 * vb.w;
        o[j] = r;
    }
}

// ---------------- launch ----------------
extern "C" void kernel_launch(void* const* d_in, const int* in_sizes, int n_in,
                              void* d_out, int out_size) {
    const float* hidden = (const float*)d_in[0];
    const int*   topk_i = (const int*)d_in[1];
    const float* topk_w = (const float*)d_in[2];
    const float* gate_w = (const float*)d_in[3];
    const float* up_w   = (const float*)d_in[4];
    const float* down_w = (const float*)d_in[5];
    float* out = (float*)d_out;

    cudaFuncSetAttribute(gemm1_kernel, cudaFuncAttributeMaxDynamicSharedMemorySize, SMEM_BYTES);
    cudaFuncSetAttribute(gemm2_kernel, cudaFuncAttributeMaxDynamicSharedMemorySize, SMEM_BYTES);

    route_kernel<<<1, 256>>>(topk_i);
    gather_kernel<<<NROWS / 16, 256>>>(hidden);
    permw1_kernel<<<E_NUM * 352, 256>>>(gate_w, up_w);
    permdw_kernel<<<E_NUM * 256, 256>>>(down_w);

    dim3 g1(I_DIM / 64, 64, E_NUM);    // (22, 64, 8)
    gemm1_kernel<<<g1, 256, SMEM_BYTES>>>();

    dim3 g2(H_DIM / 128, 64, E_NUM);   // (16, 64, 8)
    gemm2_kernel<<<g2, 256, SMEM_BYTES>>>();

    combine_kernel<<<T_TOK, 256>>>(topk_w, out);
}